// round 11
// baseline (speedup 1.0000x reference)
#include <cuda_runtime.h>
#include <math.h>

#define B_   32
#define NPTS 2048
#define L_   256
#define BIGF 1e18f
#define EPSF 1e-6f

#define LAMBDA_E_SUM       10.0f
#define LAMBDA_HIT         20.0f
#define LAMBDA_CHAMFER     0.001f
#define LAMBDA_HIT_ENTROPY 0.1f

typedef unsigned long long ull;

// ---------------- device scratch (module-load zero-initialized) ------------
__device__ float4 g_predPA[B_ * NPTS / 2];  // {-2x0,-2x1,-2y0,-2y1}
__device__ float4 g_predPB[B_ * NPTS / 2];  // {-2z0,-2z1, pn0, pn1}
__device__ float4 g_tgtPA [B_ * NPTS / 2];  // {x0,x1,y0,y1}
__device__ float4 g_tgtPB [B_ * NPTS / 2];  // {z0,z1, w0, w1} w=tn+BIG*!mask
__device__ float4 g_predS[B_ * NPTS];       // {-2x,-2y,-2z, pn}
__device__ float4 g_tgtS [B_ * NPTS];       // {  x,  y,  z, tn}
// inverted-order keys: larger key == smaller distance; 0 == +inf identity.
// combine atomically swaps keys back to 0 -> valid on every graph replay.
__device__ unsigned g_min1[B_ * NPTS];      // pred->tgt, low 11 bits = idx
__device__ unsigned g_min2[B_ * NPTS];      // tgt->pred
// race-free partial slots
__device__ float g_prep[256][4];  // blk<128: ent,kld,nhp,teh ; blk>=128: nht
__device__ float g_comb[256][2];  // blk<128: md,le ; blk>=128: s

// ---------------------------------------------------------------------------
__device__ __forceinline__ ull fma2(ull a, ull b, ull c) {
    ull d;
    asm("fma.rn.f32x2 %0, %1, %2, %3;" : "=l"(d) : "l"(a), "l"(b), "l"(c));
    return d;
}
__device__ __forceinline__ ull dup2(float x) {
    ull d;
    asm("mov.b64 %0, {%1, %1};" : "=l"(d) : "f"(x));
    return d;
}
__device__ __forceinline__ float2 unpack2(ull v) {
    float2 r;
    asm("mov.b64 {%0, %1}, %2;" : "=f"(r.x), "=f"(r.y) : "l"(v));
    return r;
}
// smaller float -> larger unsigned key (monotone inverted)
__device__ __forceinline__ unsigned encM(float f) {
    unsigned u = __float_as_uint(f);
    return ~(u ^ ((unsigned)((int)u >> 31) | 0x80000000u));
}
__device__ __forceinline__ float decM(unsigned key, unsigned& raw) {
    unsigned enc = ~key;
    unsigned m = (enc & 0x80000000u) ? 0x80000000u : 0xFFFFFFFFu;
    raw = enc ^ m;
    return __uint_as_float(raw);
}

__device__ __forceinline__ float blockReduceSum(float v, float* sh) {
    const unsigned full = 0xffffffffu;
    #pragma unroll
    for (int o = 16; o > 0; o >>= 1) v += __shfl_down_sync(full, v, o);
    int w = threadIdx.x >> 5, l = threadIdx.x & 31;
    __syncthreads();
    if (l == 0) sh[w] = v;
    __syncthreads();
    if (threadIdx.x < 32) {
        v = (threadIdx.x < (blockDim.x >> 5)) ? sh[threadIdx.x] : 0.0f;
        #pragma unroll
        for (int o = 16; o > 0; o >>= 1) v += __shfl_down_sync(full, v, o);
    }
    return v;
}

// ---------------------------------------------------------------------------
// Data transform + cheap reductions. 256 blocks:
//   [0,128)  pred side (b=blk>>2, seg=blk&3): pack + ent/kld/nhp/teh
//   [128,256) tgt side: pack + nht
__global__ __launch_bounds__(256) void prep_kernel(
    const float* __restrict__ preds, const float* __restrict__ target,
    const float* __restrict__ mask,  const float* __restrict__ mu,
    const float* __restrict__ logvar) {
    __shared__ float shr[8];
    int blk = blockIdx.x, tid = threadIdx.x;

    if (blk < 128) {
        int b = blk >> 2, seg = blk & 3;
        int jp = seg * 256 + tid;
        int n = 2 * jp;
        const float* pb = preds + (size_t)b * 5 * NPTS;
        float2 x = *(const float2*)(pb + n);
        float2 y = *(const float2*)(pb + NPTS + n);
        float2 z = *(const float2*)(pb + 2 * NPTS + n);
        float2 E = *(const float2*)(pb + 3 * NPTS + n);
        float2 h = *(const float2*)(pb + 4 * NPTS + n);
        float pn0 = x.x * x.x + y.x * y.x + z.x * z.x;
        float pn1 = x.y * x.y + y.y * y.y + z.y * z.y;
        g_predPA[b * 1024 + jp] = make_float4(-2.f * x.x, -2.f * x.y, -2.f * y.x, -2.f * y.y);
        g_predPB[b * 1024 + jp] = make_float4(-2.f * z.x, -2.f * z.y, pn0, pn1);
        g_predS[b * NPTS + n]     = make_float4(-2.f * x.x, -2.f * y.x, -2.f * z.x, pn0);
        g_predS[b * NPTS + n + 1] = make_float4(-2.f * x.y, -2.f * y.y, -2.f * z.y, pn1);
        float nhp = h.x + h.y;
        float teh = E.x * h.x + E.y * h.y;
        float ent = -(h.x * __logf(h.x + EPSF) + (1.f - h.x) * __logf(1.f - h.x + EPSF))
                    -(h.y * __logf(h.y + EPSF) + (1.f - h.y) * __logf(1.f - h.y + EPSF));
        float kld = 0.f;
        if (tid < 64) {
            int ki = blk * 64 + tid;    // 128 x 64 = 8192 = B_*L_
            float m_ = mu[ki], lv = logvar[ki];
            kld = 1.f + lv - m_ * m_ - __expf(lv);
        }
        ent = blockReduceSum(ent, shr);
        kld = blockReduceSum(kld, shr);
        nhp = blockReduceSum(nhp, shr);
        teh = blockReduceSum(teh, shr);
        if (tid == 0) {
            float* s = g_prep[blk];
            s[0] = ent; s[1] = kld; s[2] = nhp; s[3] = teh;
        }
    } else {
        int w = blk - 128;
        int b = w >> 2, seg = w & 3;
        int jp = seg * 256 + tid;
        int n = 2 * jp;
        const float* tb = target + (size_t)b * 4 * NPTS;
        float2 x = *(const float2*)(tb + n);
        float2 y = *(const float2*)(tb + NPTS + n);
        float2 z = *(const float2*)(tb + 2 * NPTS + n);
        float2 mk = *(const float2*)(mask + b * NPTS + n);
        float tn0 = x.x * x.x + y.x * y.x + z.x * z.x;
        float tn1 = x.y * x.y + y.y * y.y + z.y * z.y;
        g_tgtPA[b * 1024 + jp] = make_float4(x.x, x.y, y.x, y.y);
        g_tgtPB[b * 1024 + jp] = make_float4(z.x, z.y,
                                             tn0 + (mk.x == 0.f ? BIGF : 0.f),
                                             tn1 + (mk.y == 0.f ? BIGF : 0.f));
        g_tgtS[b * NPTS + n]     = make_float4(x.x, y.x, z.x, tn0);
        g_tgtS[b * NPTS + n + 1] = make_float4(x.y, y.y, z.y, tn1);
        float nht = blockReduceSum(mk.x + mk.y, shr);
        if (tid == 0) g_prep[blk][0] = nht;
    }
}

// ---------------------------------------------------------------------------
// Chamfer (R4 core, occ 3, init-free keys). 1024 blocks:
//   [0,512)   pass1: pred->tgt, argmin in low 11 mantissa bits
//   [512,1024) pass2: tgt->pred, plain min
// Each block: 2048 register points (8/thread) x one 128-point smem chunk.
__global__ __launch_bounds__(256, 3) void chamfer_kernel() {
    __shared__ ulonglong2 shA[64], shB[64];
    int blk = blockIdx.x, tid = threadIdx.x;
    bool isP1 = blk < 512;
    int w = isP1 ? blk : blk - 512;
    int b = w >> 4, chunk = w & 15;

    if (tid < 64) {
        const float4* PA = isP1 ? g_tgtPA : g_predPA;
        const float4* PB = isP1 ? g_tgtPB : g_predPB;
        float4 a = PA[b * 1024 + chunk * 64 + tid];
        float4 v = PB[b * 1024 + chunk * 64 + tid];
        shA[tid] = *(ulonglong2*)&a;
        shB[tid] = *(ulonglong2*)&v;
    }
    __syncthreads();

    if (isP1) {
        int pbase = b * NPTS + tid;
        ull ax2[8], ay2[8], az2[8];
        #pragma unroll
        for (int i = 0; i < 8; i++) {
            float4 p = g_predS[pbase + i * 256];
            ax2[i] = dup2(p.x); ay2[i] = dup2(p.y); az2[i] = dup2(p.z);
        }
        float bl[8], bh[8];
        #pragma unroll
        for (int i = 0; i < 8; i++) { bl[i] = 3.4e38f; bh[i] = 3.4e38f; }

        unsigned jlo = (unsigned)(chunk * 128);
        #pragma unroll 8
        for (int j = 0; j < 64; j++) {
            ulonglong2 A = shA[j], Bv = shB[j];
            unsigned jhi = jlo | 1u;
            #pragma unroll
            for (int i = 0; i < 8; i++) {
                ull t = fma2(az2[i], Bv.x, Bv.y);
                t = fma2(ay2[i], A.y, t);
                t = fma2(ax2[i], A.x, t);
                float2 v = unpack2(t);
                unsigned elo = (__float_as_uint(v.x) & 0xFFFFF800u) | jlo;
                unsigned ehi = (__float_as_uint(v.y) & 0xFFFFF800u) | jhi;
                bl[i] = fminf(bl[i], __uint_as_float(elo));
                bh[i] = fminf(bh[i], __uint_as_float(ehi));
            }
            jlo += 2;
        }
        #pragma unroll
        for (int i = 0; i < 8; i++)
            atomicMax(&g_min1[pbase + i * 256], encM(fminf(bl[i], bh[i])));
    } else {
        int tbase = b * NPTS + tid;
        ull tx2[8], ty2[8], tz2[8];
        #pragma unroll
        for (int i = 0; i < 8; i++) {
            float4 t = g_tgtS[tbase + i * 256];
            tx2[i] = dup2(t.x); ty2[i] = dup2(t.y); tz2[i] = dup2(t.z);
        }
        float bl[8], bh[8];
        #pragma unroll
        for (int i = 0; i < 8; i++) { bl[i] = 3.4e38f; bh[i] = 3.4e38f; }

        #pragma unroll 8
        for (int j = 0; j < 64; j++) {
            ulonglong2 A = shA[j], Bv = shB[j];
            #pragma unroll
            for (int i = 0; i < 8; i++) {
                ull t = fma2(tz2[i], Bv.x, Bv.y);
                t = fma2(ty2[i], A.y, t);
                t = fma2(tx2[i], A.x, t);
                float2 v = unpack2(t);
                bl[i] = fminf(bl[i], v.x);
                bh[i] = fminf(bh[i], v.y);
            }
        }
        #pragma unroll
        for (int i = 0; i < 8; i++)
            atomicMax(&g_min2[tbase + i * 256], encM(fminf(bl[i], bh[i])));
    }
}

// ---------------------------------------------------------------------------
// Lean combine (no ticket). 256 blocks, 512 points each:
//   [0,128)  pred side: minD_pred, |dE|
//   [128,256) tgt side: minD_tgt*mask
__global__ __launch_bounds__(256) void combine_kernel(
    const float* __restrict__ preds, const float* __restrict__ target,
    const float* __restrict__ mask) {
    __shared__ float shr[8];
    int blk = blockIdx.x, tid = threadIdx.x;

    if (blk < 128) {
        int b = blk >> 2, seg = blk & 3;
        const float* pb = preds + (size_t)b * 5 * NPTS;
        const float* tE = target + (size_t)b * 4 * NPTS + 3 * NPTS;
        float md = 0.f, le = 0.f;
        #pragma unroll
        for (int r = 0; r < 2; r++) {
            int n = seg * 512 + r * 256 + tid;
            int gidx = b * NPTS + n;
            unsigned raw;
            unsigned key = atomicExch(&g_min1[gidx], 0u);  // read + reset
            float best = decM(key, raw);
            int idx = (int)(raw & 0x7FFu);
            md += fmaxf(g_predS[gidx].w + best, 0.f);
            le += fabsf(pb[3 * NPTS + n] - tE[idx]);
        }
        md = blockReduceSum(md, shr);
        le = blockReduceSum(le, shr);
        if (tid == 0) { g_comb[blk][0] = md; g_comb[blk][1] = le; }
    } else {
        int w = blk - 128;
        int b = w >> 2, seg = w & 3;
        float s = 0.f;
        #pragma unroll
        for (int r = 0; r < 2; r++) {
            int m = seg * 512 + r * 256 + tid;
            int gidx = b * NPTS + m;
            unsigned raw;
            unsigned key = atomicExch(&g_min2[gidx], 0u);
            float best = decM(key, raw);
            s += fmaxf(g_tgtS[gidx].w + best, 0.f) * mask[gidx];
        }
        s = blockReduceSum(s, shr);
        if (tid == 0) g_comb[blk][0] = s;
    }
}

// ---------------------------------------------------------------------------
// Final: 1 block, aggregate slots + write output.
__global__ __launch_bounds__(256) void final_kernel(
    const float* __restrict__ e_init, const float* __restrict__ kl_weight,
    float* __restrict__ out, int out_size) {
    __shared__ float shr[8];
    int tid = threadIdx.x;

    float vMD = blockReduceSum(tid < 128 ? g_comb[tid][0] : 0.f, shr);
    float vLE = blockReduceSum(tid < 128 ? g_comb[tid][1] : 0.f, shr);
    float vS  = blockReduceSum(tid >= 128 ? g_comb[tid][0] : 0.f, shr);
    float vEN = blockReduceSum(tid < 128 ? g_prep[tid][0] : 0.f, shr);
    float vKL = blockReduceSum(tid < 128 ? g_prep[tid][1] : 0.f, shr);
    float vNH = blockReduceSum(tid >= 128 ? g_prep[tid][0] : 0.f, shr);

    float dh2 = 0.f, de2 = 0.f;
    if (tid < B_) {
        float nhp = 0.f, teh = 0.f, nht = 0.f;
        #pragma unroll
        for (int s2 = 0; s2 < 4; s2++) {
            nhp += g_prep[4 * tid + s2][2];
            teh += g_prep[4 * tid + s2][3];
            nht += g_prep[128 + 4 * tid + s2][0];
        }
        float dh = nhp - nht;
        float de = teh - e_init[tid];
        dh2 = dh * dh; de2 = de * de;
    }
    if (tid < 32) {
        const unsigned full = 0xffffffffu;
        #pragma unroll
        for (int o = 16; o > 0; o >>= 1) {
            dh2 += __shfl_down_sync(full, dh2, o);
            de2 += __shfl_down_sync(full, de2, o);
        }
    }
    if (tid == 0) {
        float chamP = vMD / (float)(B_ * NPTS);
        float chamT = vS / vNH;
        float loss_chamf = (chamT + chamP) * LAMBDA_CHAMFER;
        float localE = vLE / (float)(B_ * NPTS);
        float ge   = LAMBDA_E_SUM * de2 / (float)B_;
        float hit  = LAMBDA_HIT   * dh2 / (float)B_;
        float entr = LAMBDA_HIT_ENTROPY * vEN / (float)(B_ * NPTS);
        float kl   = kl_weight[0] * (-0.5f * vKL / (float)B_);
        float total = loss_chamf + localE + kl + ge + hit + entr;

        if (out_size >= 6) {
            out[0] = total;
            out[1] = loss_chamf;
            out[2] = localE;
            out[3] = ge;
            out[4] = hit;
            out[5] = kl;
        } else if (out_size == 5) {
            out[0] = loss_chamf; out[1] = localE; out[2] = ge;
            out[3] = hit;        out[4] = kl;
        } else {
            out[0] = total;
        }
    }
}

// ---------------------------------------------------------------------------
extern "C" void kernel_launch(void* const* d_in, const int* in_sizes, int n_in,
                              void* d_out, int out_size) {
    const float* preds  = (const float*)d_in[0];
    const float* target = (const float*)d_in[1];
    const float* tmask  = (const float*)d_in[2];
    const float* mu     = (const float*)d_in[3];
    const float* logvar = (const float*)d_in[4];
    const float* e_init = (const float*)d_in[5];
    const float* klw    = (const float*)d_in[6];
    float* out = (float*)d_out;

    prep_kernel<<<256, 256>>>(preds, target, tmask, mu, logvar);
    chamfer_kernel<<<1024, 256>>>();
    combine_kernel<<<256, 256>>>(preds, target, tmask);
    final_kernel<<<1, 256>>>(e_init, klw, out, out_size);
}